// round 1
// baseline (speedup 1.0000x reference)
#include <cuda_runtime.h>
#include <cuda_bf16.h>
#include <math_constants.h>

#define N_NODES 50000
#define N_EDGES 800000
#define HID 128
#define PW 384   // columns of fused precompute: [0:128)=z@Ws, [128:256)=z@Wd, [256:384)=z@W1a

// ---------------- scratch (static device allocations are allowed) ----------------
__device__ float g_P[(size_t)N_NODES * PW];       // fused precompute  (76.8 MB)
__device__ float g_agg[(size_t)N_NODES * HID];    // aggregated messages
__device__ float g_hidden[(size_t)N_NODES * HID]; // hidden layer
__device__ float g_Wcat[HID * PW];                // [Ws | Wd | W1a] concatenated, row-major [128,384]
__device__ int   g_count[N_NODES];
__device__ int   g_offset[N_NODES];
__device__ int   g_cursor[N_NODES];
__device__ int   g_sorted_src[N_EDGES];
__device__ float g_sorted_w[N_EDGES];

// ---------------- small prep kernels ----------------
__global__ void zero_count_kernel() {
    int i = blockIdx.x * blockDim.x + threadIdx.x;
    if (i < N_NODES) g_count[i] = 0;
}

// Wcat[k][j]: j<128 -> Ws[k][j] = Wm[(128+k)*128+j]; 128<=j<256 -> Wd[k][j-128] = Wm[k*128+(j-128)];
//             j>=256 -> W1a[k][j-256] = W1[k*128+(j-256)]
__global__ void build_wcat_kernel(const float* __restrict__ Wm, const float* __restrict__ W1) {
    int idx = blockIdx.x * blockDim.x + threadIdx.x;
    if (idx >= HID * PW) return;
    int k = idx / PW;
    int j = idx % PW;
    float v;
    if (j < 128)       v = Wm[(128 + k) * 128 + j];
    else if (j < 256)  v = Wm[k * 128 + (j - 128)];
    else               v = W1[k * 128 + (j - 256)];
    g_Wcat[idx] = v;
}

// ---------------- generic fp32 SGEMM: out = f(A@B [+ bias] [+ Cadd]) ----------------
// A: [M,K] row-major (lda=K). B: [K,N] row-major (ldb=N). out: [M,N].
#define BM 128
#define BN 128
#define BKK 8

__global__ __launch_bounds__(256, 2)
void gemm_kernel(const float* __restrict__ A, const float* __restrict__ B,
                 const float* __restrict__ bias, const float* __restrict__ Cadd,
                 int ldCadd, float* __restrict__ out,
                 int M, int N, int K, int relu)
{
    __shared__ float As[BKK][BM];
    __shared__ float Bs[BKK][BN];

    const int tid = threadIdx.x;
    const int bm0 = blockIdx.x * BM;
    const int bn0 = blockIdx.y * BN;
    const int tx = tid & 15;        // 0..15
    const int ty = tid >> 4;        // 0..15

    // loaders
    const int arow = tid >> 1;              // 0..127
    const int acol = (tid & 1) * 4;         // 0 or 4
    const int brow = tid >> 5;              // 0..7
    const int bcol = (tid & 31) * 4;        // 0..124

    float acc[8][8];
#pragma unroll
    for (int i = 0; i < 8; i++)
#pragma unroll
        for (int j = 0; j < 8; j++) acc[i][j] = 0.0f;

    for (int k0 = 0; k0 < K; k0 += BKK) {
        // load A tile (guard rows), store transposed
        int gr = bm0 + arow;
        float4 av = make_float4(0.f, 0.f, 0.f, 0.f);
        if (gr < M) av = *(const float4*)(A + (size_t)gr * K + k0 + acol);
        As[acol + 0][arow] = av.x;
        As[acol + 1][arow] = av.y;
        As[acol + 2][arow] = av.z;
        As[acol + 3][arow] = av.w;
        // load B tile (K always full, N divisible by BN)
        float4 bv = *(const float4*)(B + (size_t)(k0 + brow) * N + bn0 + bcol);
        *(float4*)(&Bs[brow][bcol]) = bv;
        __syncthreads();

#pragma unroll
        for (int k = 0; k < BKK; k++) {
            float a[8], b[8];
            *(float4*)(a)     = *(const float4*)(&As[k][ty * 4]);
            *(float4*)(a + 4) = *(const float4*)(&As[k][64 + ty * 4]);
            *(float4*)(b)     = *(const float4*)(&Bs[k][tx * 4]);
            *(float4*)(b + 4) = *(const float4*)(&Bs[k][64 + tx * 4]);
#pragma unroll
            for (int i = 0; i < 8; i++)
#pragma unroll
                for (int j = 0; j < 8; j++)
                    acc[i][j] = fmaf(a[i], b[j], acc[i][j]);
        }
        __syncthreads();
    }

    // epilogue (split-tile mapping: rows {ty*4+i, 64+ty*4+i}, cols {tx*4+j, 64+tx*4+j})
#pragma unroll
    for (int ih = 0; ih < 2; ih++) {
#pragma unroll
        for (int i = 0; i < 4; i++) {
            int r = bm0 + ih * 64 + ty * 4 + i;
            if (r >= M) continue;
#pragma unroll
            for (int jh = 0; jh < 2; jh++) {
                int c = bn0 + jh * 64 + tx * 4;
                float4 v;
                v.x = acc[ih * 4 + i][jh * 4 + 0];
                v.y = acc[ih * 4 + i][jh * 4 + 1];
                v.z = acc[ih * 4 + i][jh * 4 + 2];
                v.w = acc[ih * 4 + i][jh * 4 + 3];
                if (bias) {
                    v.x += bias[c + 0]; v.y += bias[c + 1];
                    v.z += bias[c + 2]; v.w += bias[c + 3];
                }
                if (Cadd) {
                    const float* cp = Cadd + (size_t)r * ldCadd + c;
                    v.x += cp[0]; v.y += cp[1]; v.z += cp[2]; v.w += cp[3];
                }
                if (relu) {
                    v.x = fmaxf(v.x, 0.f); v.y = fmaxf(v.y, 0.f);
                    v.z = fmaxf(v.z, 0.f); v.w = fmaxf(v.w, 0.f);
                }
                *(float4*)(out + (size_t)r * N + c) = v;
            }
        }
    }
}

// ---------------- edge counting sort ----------------
__global__ void hist_kernel(const int* __restrict__ edst) {
    int i = blockIdx.x * blockDim.x + threadIdx.x;
    if (i < N_EDGES) atomicAdd(&g_count[edst[i]], 1);
}

__global__ void scan_kernel() {
    const int T = 1024;
    const int C = (N_NODES + T - 1) / T;  // 49
    int t = threadIdx.x;
    int s = t * C;
    int e = min(s + C, N_NODES);
    int sum = 0;
    for (int i = s; i < e; i++) sum += g_count[i];

    int lane = t & 31, warp = t >> 5;
    int incl = sum;
#pragma unroll
    for (int o = 1; o < 32; o <<= 1) {
        int v = __shfl_up_sync(0xffffffffu, incl, o);
        if (lane >= o) incl += v;
    }
    __shared__ int wsum[32];
    if (lane == 31) wsum[warp] = incl;
    __syncthreads();
    if (warp == 0) {
        int v = wsum[lane];
        int wi = v;
#pragma unroll
        for (int o = 1; o < 32; o <<= 1) {
            int u = __shfl_up_sync(0xffffffffu, wi, o);
            if (lane >= o) wi += u;
        }
        wsum[lane] = wi - v;  // exclusive
    }
    __syncthreads();
    int run = wsum[warp] + (incl - sum);
    for (int i = s; i < e; i++) {
        g_offset[i] = run;
        g_cursor[i] = run;
        run += g_count[i];
    }
}

__global__ void scatter_kernel(const int* __restrict__ esrc, const int* __restrict__ edst,
                               const float* __restrict__ ew) {
    int i = blockIdx.x * blockDim.x + threadIdx.x;
    if (i >= N_EDGES) return;
    int d = edst[i];
    int pos = atomicAdd(&g_cursor[d], 1);
    g_sorted_src[pos] = esrc[i];
    g_sorted_w[pos] = ew[i];
}

// ---------------- per-node max aggregation (1 warp / node, no atomics) ----------------
__global__ void agg_kernel(const float* __restrict__ Wm, const float* __restrict__ bm) {
    int gw = (blockIdx.x * blockDim.x + threadIdx.x) >> 5;
    int lane = threadIdx.x & 31;
    if (gw >= N_NODES) return;

    int start = g_offset[gw];
    int cnt = g_count[gw];
    float4 outv = make_float4(0.f, 0.f, 0.f, 0.f);
    if (cnt > 0) {
        float4 w4 = *(const float4*)(Wm + 256 * 128 + lane * 4);  // ww
        float4 m = make_float4(-CUDART_INF_F, -CUDART_INF_F, -CUDART_INF_F, -CUDART_INF_F);
        int e = start, end = start + cnt;
        for (; e < end; e++) {
            int s = g_sorted_src[e];
            float w = g_sorted_w[e];
            float4 p = *(const float4*)(g_P + (size_t)s * PW + lane * 4);  // z@Ws row
            m.x = fmaxf(m.x, fmaf(w, w4.x, p.x));
            m.y = fmaxf(m.y, fmaf(w, w4.y, p.y));
            m.z = fmaxf(m.z, fmaf(w, w4.z, p.z));
            m.w = fmaxf(m.w, fmaf(w, w4.w, p.w));
        }
        float4 q = *(const float4*)(g_P + (size_t)gw * PW + 128 + lane * 4);  // z@Wd row
        float4 b = *(const float4*)(bm + lane * 4);
        outv.x = q.x + b.x + m.x;
        outv.y = q.y + b.y + m.y;
        outv.z = q.z + b.z + m.z;
        outv.w = q.w + b.w + m.w;
    }
    *(float4*)(g_agg + (size_t)gw * HID + lane * 4) = outv;
}

// ---------------- launch ----------------
extern "C" void kernel_launch(void* const* d_in, const int* in_sizes, int n_in,
                              void* d_out, int out_size) {
    const float* z    = (const float*)d_in[0];
    const float* ew   = (const float*)d_in[1];
    const int*   esrc = (const int*)d_in[2];
    const int*   edst = (const int*)d_in[3];
    const float* Wm   = (const float*)d_in[4];
    const float* bm   = (const float*)d_in[5];
    const float* W1   = (const float*)d_in[6];
    const float* b1   = (const float*)d_in[7];
    const float* W2   = (const float*)d_in[8];
    const float* b2   = (const float*)d_in[9];
    float* out = (float*)d_out;

    float *P, *AGG, *HIDN, *WCAT;
    cudaGetSymbolAddress((void**)&P, g_P);
    cudaGetSymbolAddress((void**)&AGG, g_agg);
    cudaGetSymbolAddress((void**)&HIDN, g_hidden);
    cudaGetSymbolAddress((void**)&WCAT, g_Wcat);

    zero_count_kernel<<<(N_NODES + 255) / 256, 256>>>();
    build_wcat_kernel<<<(HID * PW + 255) / 256, 256>>>(Wm, W1);

    // P[:, 0:128]=z@Ws, [128:256)=z@Wd, [256:384)=z@W1a
    gemm_kernel<<<dim3((N_NODES + BM - 1) / BM, PW / BN), 256>>>(
        z, WCAT, nullptr, nullptr, 0, P, N_NODES, PW, HID, 0);

    hist_kernel<<<N_EDGES / 256, 256>>>(edst);
    scan_kernel<<<1, 1024>>>();
    scatter_kernel<<<N_EDGES / 256, 256>>>(esrc, edst, ew);
    agg_kernel<<<(N_NODES * 32) / 256, 256>>>(Wm, bm);

    // hidden = relu(agg @ W1b + b1 + P[:,256:384])
    gemm_kernel<<<dim3((N_NODES + BM - 1) / BM, HID / BN), 256>>>(
        AGG, W1 + 128 * 128, b1, P + 256, PW, HIDN, N_NODES, HID, HID, 1);

    // out = hidden @ W2 + b2
    gemm_kernel<<<dim3((N_NODES + BM - 1) / BM, HID / BN), 256>>>(
        HIDN, W2, b2, nullptr, 0, out, N_NODES, HID, HID, 0);
}